// round 14
// baseline (speedup 1.0000x reference)
#include <cuda_runtime.h>
#include <cuda_bf16.h>
#include <math.h>
#include <cstdint>

#define BSZ   4096
#define DIM   768
#define COMPS 16384
#define GRD   128

// ---------------- device scratch ----------------
__device__ float g_T[COMPS * DIM];
__device__ float g_wn[COMPS];
__device__ float g_cnt[COMPS];
__device__ float g_s1[COMPS];
__device__ float g_s[COMPS];
__device__ float g_G[GRD * GRD];
__device__ int   g_bmu[BSZ];
__device__ __align__(16) __nv_bfloat16 g_Xb[BSZ * DIM];
__device__ __align__(16) __nv_bfloat16 g_Wb[COMPS * DIM];
__device__ __align__(16) float4 g_top2[(size_t)BSZ * 128];   // per (row, coltile): v0,i0,v1,i1

// ---------------- helpers ----------------
__device__ __forceinline__ uint32_t smem_to_u32(const void* p) {
    uint32_t a;
    asm("{ .reg .u64 t; cvta.to.shared.u64 t, %1; cvt.u32.u64 %0, t; }" : "=r"(a) : "l"(p));
    return a;
}
__device__ __forceinline__ void cp_async16(uint32_t dst, const void* src) {
    asm volatile("cp.async.cg.shared.global [%0], [%1], 16;" :: "r"(dst), "l"(src));
}
__device__ __forceinline__ void ldmatrix_x4(uint32_t& r0, uint32_t& r1, uint32_t& r2,
                                            uint32_t& r3, uint32_t addr) {
    asm volatile("ldmatrix.sync.aligned.m8n8.x4.shared.b16 {%0,%1,%2,%3}, [%4];"
                 : "=r"(r0), "=r"(r1), "=r"(r2), "=r"(r3) : "r"(addr));
}
__device__ __forceinline__ void mma_bf16(float* d, const uint32_t* a, const uint32_t* b) {
    asm volatile(
        "mma.sync.aligned.m16n8k16.row.col.f32.bf16.bf16.f32 "
        "{%0,%1,%2,%3}, {%4,%5,%6,%7}, {%8,%9}, {%0,%1,%2,%3};"
        : "+f"(d[0]), "+f"(d[1]), "+f"(d[2]), "+f"(d[3])
        : "r"(a[0]), "r"(a[1]), "r"(a[2]), "r"(a[3]), "r"(b[0]), "r"(b[1]));
}
__device__ __forceinline__ unsigned long long pack2(float lo, float hi) {
    unsigned long long r;
    asm("mov.b64 %0, {%1, %2};" : "=l"(r) : "r"(__float_as_uint(lo)), "r"(__float_as_uint(hi)));
    return r;
}
__device__ __forceinline__ void ffma2(unsigned long long& d, unsigned long long a,
                                      unsigned long long b) {
    asm("fma.rn.f32x2 %0, %1, %2, %0;" : "+l"(d) : "l"(a), "l"(b));
}
__device__ __forceinline__ void unpack2(unsigned long long p, float& lo, float& hi) {
    unsigned l, h;
    asm("mov.b64 {%0, %1}, %2;" : "=r"(l), "=r"(h) : "l"(p));
    lo = __uint_as_float(l); hi = __uint_as_float(h);
}

// ---------------- pre kernels ----------------
#define XN4 (BSZ * DIM / 4)
#define WN4 (COMPS * DIM / 4)

__global__ void cvtX_kernel(const float* __restrict__ src) {
    int i = blockIdx.x * blockDim.x + threadIdx.x;
    if (i >= XN4) return;
    float4 v = *(const float4*)(src + (size_t)i * 4);
    ushort4 o;
    o.x = __bfloat16_as_ushort(__float2bfloat16(v.x));
    o.y = __bfloat16_as_ushort(__float2bfloat16(v.y));
    o.z = __bfloat16_as_ushort(__float2bfloat16(v.z));
    o.w = __bfloat16_as_ushort(__float2bfloat16(v.w));
    *(ushort4*)(g_Xb + (size_t)i * 4) = o;
}

__global__ void cvtW_wnorm_kernel(const float* __restrict__ W) {
    int row = blockIdx.x * 8 + (threadIdx.x >> 5);
    int lane = threadIdx.x & 31;
    const float* wr = W + (size_t)row * DIM;
    float s = 0.f;
    #pragma unroll
    for (int k = 0; k < 6; k++) {
        int e = lane * 4 + k * 128;
        float4 v = *(const float4*)(wr + e);
        s = fmaf(v.x, v.x, s); s = fmaf(v.y, v.y, s);
        s = fmaf(v.z, v.z, s); s = fmaf(v.w, v.w, s);
        ushort4 o;
        o.x = __bfloat16_as_ushort(__float2bfloat16(v.x));
        o.y = __bfloat16_as_ushort(__float2bfloat16(v.y));
        o.z = __bfloat16_as_ushort(__float2bfloat16(v.z));
        o.w = __bfloat16_as_ushort(__float2bfloat16(v.w));
        *(ushort4*)(g_Wb + (size_t)row * DIM + e) = o;
    }
    #pragma unroll
    for (int o = 16; o; o >>= 1) s += __shfl_xor_sync(0xffffffffu, s, o);
    if (lane == 0) g_wn[row] = s;
}

__global__ void gmat_kernel(const int* __restrict__ itp) {
    float decay = 1.f - (float)(*itp) / 1000.f;
    float sig = 64.f * decay;
    int a = blockIdx.x, b = threadIdx.x;
    float d = (float)(a - b);
    g_G[a * GRD + b] = expf(-(d * d) / (sig * sig));
}

// ---------------- bf16 BMU GEMM: 128x128 tiles, 2 CTAs/SM, 4 stages ------
// K chunk = 16 halfs = 32B/row, padded pitch 48B. Stage = A 6144 + B 6144.
// Fragment loads via ldmatrix.x4 (conflict-free with 48B pitch).
#define QPITCH  48
#define QT_TILE 6144
#define QSTAGE  12288
#define QWNS    (4 * QSTAGE)     // 49152
#define QSMEM   (QWNS + 512)     // 49664
#define NKCH    (DIM / 16)       // 48

#define INS2(v, i)                                            \
    do {                                                      \
        float _v = (v); int _i = (i);                         \
        if (_v < v0) { v1 = v0; i1 = i0; v0 = _v; i0 = _i; }  \
        else if (_v < v1) { v1 = _v; i1 = _i; }               \
    } while (0)

__global__ __launch_bounds__(256, 2) void bmu_b_kernel() {
    extern __shared__ char sm[];
    const uint32_t sb = smem_to_u32(sm);
    const int t = threadIdx.x, lane = t & 31, w = t >> 5;
    const int wm = w >> 2, wn_ = w & 3;
    const int arow = lane >> 2;
    const int bx = blockIdx.x, by = blockIdx.y;
    const int rowX = by * 128, rowW = bx * 128;

    float* wns = (float*)(sm + QWNS);
    if (t < 128) wns[t] = g_wn[rowW + t];

    // ldmatrix lane-offsets (bytes into tile)
    const int alr = lane & 15, ahalf = (lane >> 4) * 16;
    uint32_t aoff[4];
    #pragma unroll
    for (int mi = 0; mi < 4; mi++)
        aoff[mi] = (uint32_t)((wm * 64 + mi * 16 + alr) * QPITCH + ahalf);
    const int blr = lane & 7, bk = ((lane >> 3) & 1) * 16, bhi = lane >> 4;
    uint32_t boff[2];
    #pragma unroll
    for (int pi = 0; pi < 2; pi++)
        boff[pi] = (uint32_t)((wn_ * 32 + (2 * pi + bhi) * 8 + blr) * QPITCH + bk);

    float acc[4][4][4];
    #pragma unroll
    for (int mi = 0; mi < 4; mi++)
        #pragma unroll
        for (int ni = 0; ni < 4; ni++)
            #pragma unroll
            for (int k = 0; k < 4; k++) acc[mi][ni][k] = 0.f;

    auto load_stage = [&](int s, int c) {
        uint32_t base = sb + s * QSTAGE;
        int r = t >> 1, g = t & 1;
        cp_async16(base + r * QPITCH + g * 16,
                   g_Xb + (size_t)(rowX + r) * DIM + c * 16 + g * 8);
        cp_async16(base + QT_TILE + r * QPITCH + g * 16,
                   g_Wb + (size_t)(rowW + r) * DIM + c * 16 + g * 8);
    };
    auto compute = [&](int s) {
        uint32_t Ah = sb + s * QSTAGE;
        uint32_t Bh = Ah + QT_TILE;
        uint32_t b[4][2];
        ldmatrix_x4(b[0][0], b[0][1], b[1][0], b[1][1], Bh + boff[0]);
        ldmatrix_x4(b[2][0], b[2][1], b[3][0], b[3][1], Bh + boff[1]);
        uint32_t a[4][4];
        #pragma unroll
        for (int mi = 0; mi < 4; mi++)
            ldmatrix_x4(a[mi][0], a[mi][1], a[mi][2], a[mi][3], Ah + aoff[mi]);
        #pragma unroll
        for (int mi = 0; mi < 4; mi++)
            #pragma unroll
            for (int ni = 0; ni < 4; ni++) mma_bf16(acc[mi][ni], a[mi], b[ni]);
    };

    #pragma unroll
    for (int p = 0; p < 3; p++) { load_stage(p, p); asm volatile("cp.async.commit_group;"); }
    for (int c = 0; c < NKCH; c++) {
        asm volatile("cp.async.wait_group 2;");
        __syncthreads();
        if (c + 3 < NKCH) load_stage((c + 3) & 3, c + 3);
        asm volatile("cp.async.commit_group;");
        compute(c & 3);
    }

    // ---- epilogue: per-row top-2 of d2 = wn - 2*dot over 128 cols ----
    __syncthreads();                       // stage smem free for reuse
    float4* top2s = (float4*)sm;           // [128 rows][4 warps]

    #pragma unroll
    for (int mi = 0; mi < 4; mi++) {
        #pragma unroll
        for (int h = 0; h < 2; h++) {
            float v0 = 3.4e38f, v1 = 3.4e38f;
            int i0 = 0x7fffffff, i1 = 0x7fffffff;
            #pragma unroll
            for (int ni = 0; ni < 4; ni++) {
                #pragma unroll
                for (int cc = 0; cc < 2; cc++) {
                    int col = wn_ * 32 + ni * 8 + (lane & 3) * 2 + cc;
                    float d2 = wns[col] - 2.f * acc[mi][ni][h * 2 + cc];
                    INS2(d2, rowW + col);
                }
            }
            #pragma unroll
            for (int o = 1; o < 4; o <<= 1) {
                float ov0 = __shfl_xor_sync(0xffffffffu, v0, o);
                int   oi0 = __shfl_xor_sync(0xffffffffu, i0, o);
                float ov1 = __shfl_xor_sync(0xffffffffu, v1, o);
                int   oi1 = __shfl_xor_sync(0xffffffffu, i1, o);
                INS2(ov0, oi0);
                INS2(ov1, oi1);
            }
            if ((lane & 3) == 0) {
                int rr = wm * 64 + mi * 16 + h * 8 + arow;
                top2s[rr * 4 + wn_] = make_float4(v0, __int_as_float(i0),
                                                  v1, __int_as_float(i1));
            }
        }
    }
    __syncthreads();
    if (t < 128) {
        float4 a0 = top2s[t * 4 + 0];
        float v0 = a0.x, v1 = a0.z;
        int i0 = __float_as_int(a0.y), i1 = __float_as_int(a0.w);
        #pragma unroll
        for (int j = 1; j < 4; j++) {
            float4 aj = top2s[t * 4 + j];
            INS2(aj.x, __float_as_int(aj.y));
            INS2(aj.z, __float_as_int(aj.w));
        }
        g_top2[(size_t)(rowX + t) * 128 + bx] =
            make_float4(v0, __int_as_float(i0), v1, __int_as_float(i1));
    }
}

// ---------------- candidate rescue: min + margin over top-2 + exact fp32 --
#define MARGIN_F 2.0f
__global__ __launch_bounds__(128) void bmu_scan_kernel(const float* __restrict__ X,
                                                       const float* __restrict__ W) {
    __shared__ float red[128];
    __shared__ int cnt;
    __shared__ int cand[128];
    int row = blockIdx.x, t = threadIdx.x;
    float4 e = g_top2[(size_t)row * 128 + t];

    red[t] = e.x;
    __syncthreads();
    for (int s = 64; s; s >>= 1) {
        if (t < s) red[t] = fminf(red[t], red[t + s]);
        __syncthreads();
    }
    float thr = red[0] + MARGIN_F;
    if (t == 0) cnt = 0;
    __syncthreads();
    if (e.x <= thr) { int p = atomicAdd(&cnt, 1); if (p < 128) cand[p] = __float_as_int(e.y); }
    if (e.z <= thr) { int p = atomicAdd(&cnt, 1); if (p < 128) cand[p] = __float_as_int(e.w); }
    __syncthreads();
    int n = min(cnt, 128);
    if (t < 32) {
        const float* xr = X + (size_t)row * DIM;
        float bv = 3.4e38f; int bi = 0x7fffffff;
        for (int k = 0; k < n; k++) {
            int c = cand[k];
            const float* wr = W + (size_t)c * DIM;
            float s = 0.f;
            #pragma unroll
            for (int m = 0; m < 24; m++)
                s = fmaf(xr[t + m * 32], wr[t + m * 32], s);
            #pragma unroll
            for (int o = 16; o; o >>= 1) s += __shfl_xor_sync(0xffffffffu, s, o);
            float d2 = g_wn[c] - 2.f * s;
            if (d2 < bv || (d2 == bv && c < bi)) { bv = d2; bi = c; }
        }
        if (t == 0) g_bmu[row] = bi;
    }
}

__global__ void scatter_kernel(const float* __restrict__ X) {
    int b = blockIdx.x;
    int u = g_bmu[b];
    const float* xr = X + (size_t)b * DIM;
    float* tr = g_T + (size_t)u * DIM;
    for (int d = threadIdx.x; d < DIM; d += blockDim.x)
        atomicAdd(&tr[d], xr[d]);
    if (threadIdx.x == 0) atomicAdd(&g_cnt[u], 1.f);
}

// ---------------- separable Gaussian conv via packed f32x2, in place ------
__global__ __launch_bounds__(256) void conv_kernel(int rstride) {
    __shared__ float Ts[16][64];
    __shared__ float Gs[16][128];
    int t = threadIdx.x;
    size_t base = (size_t)blockIdx.y * (GRD * DIM) + (size_t)blockIdx.x * 64;
    int cg = t & 15, rg = t >> 4;
    int lk = t >> 4, lc = (t & 15) * 4, gi = (t & 15) * 8;

    unsigned long long acc2[8][2];
    #pragma unroll
    for (int r = 0; r < 8; r++) { acc2[r][0] = 0ull; acc2[r][1] = 0ull; }

    for (int k0 = 0; k0 < GRD; k0 += 16) {
        if (k0) __syncthreads();
        *(float4*)&Ts[lk][lc]     = *(const float4*)&g_T[base + (size_t)(k0 + lk) * rstride + lc];
        *(float4*)&Gs[lk][gi]     = *(const float4*)&g_G[(k0 + lk) * GRD + gi];
        *(float4*)&Gs[lk][gi + 4] = *(const float4*)&g_G[(k0 + lk) * GRD + gi + 4];
        __syncthreads();
        #pragma unroll
        for (int k = 0; k < 16; k++) {
            float4 tv = *(const float4*)&Ts[k][cg * 4];
            unsigned long long b0 = pack2(tv.x, tv.y);
            unsigned long long b1 = pack2(tv.z, tv.w);
            #pragma unroll
            for (int r = 0; r < 8; r++) {
                float g = Gs[k][rg * 8 + r];
                unsigned long long gp = pack2(g, g);
                ffma2(acc2[r][0], gp, b0);
                ffma2(acc2[r][1], gp, b1);
            }
        }
    }
    #pragma unroll
    for (int r = 0; r < 8; r++) {
        float4 o;
        unpack2(acc2[r][0], o.x, o.y);
        unpack2(acc2[r][1], o.z, o.w);
        *(float4*)&g_T[base + (size_t)(rg * 8 + r) * rstride + cg * 4] = o;
    }
}

__global__ void convs1_kernel() {
    int ip = blockIdx.x, j = threadIdx.x;
    float s = 0.f;
    for (int i = 0; i < GRD; i++)
        s = fmaf(g_G[ip * GRD + i], g_cnt[i * GRD + j], s);
    g_s1[ip * GRD + j] = s;
}
__global__ void convs2_kernel() {
    int i = blockIdx.x, jp = threadIdx.x;
    float s = 0.f;
    for (int j = 0; j < GRD; j++)
        s = fmaf(g_G[j * GRD + jp], g_s1[i * GRD + j], s);
    g_s[i * GRD + jp] = s;
}

__global__ void final_kernel(const float* __restrict__ W, float* __restrict__ out,
                             const int* __restrict__ itp) {
    float decay = 1.f - (float)(*itp) / 1000.f;
    float alpha = 0.3f * decay;
    int idx = blockIdx.x * blockDim.x + threadIdx.x;
    int i4 = idx * 4;
    if (i4 >= COMPS * DIM) return;
    int c = i4 / DIM;
    float m = 1.f - alpha * g_s[c];
    float4 w = *(const float4*)(W + i4);
    float4 v = *(const float4*)(g_T + i4);
    float4 o = make_float4(w.x * m + alpha * v.x, w.y * m + alpha * v.y,
                           w.z * m + alpha * v.z, w.w * m + alpha * v.w);
    *(float4*)(out + i4) = o;
}

// ---------------- launch ----------------
extern "C" void kernel_launch(void* const* d_in, const int* in_sizes, int n_in,
                              void* d_out, int out_size) {
    const float* X   = (const float*)d_in[0];
    const float* W   = (const float*)d_in[1];
    const int*   itp = (const int*)d_in[2];
    float* out = (float*)d_out;

    cudaFuncSetAttribute(bmu_b_kernel, cudaFuncAttributeMaxDynamicSharedMemorySize, QSMEM);

    float *tPtr, *cntPtr;
    cudaGetSymbolAddress((void**)&tPtr, g_T);
    cudaGetSymbolAddress((void**)&cntPtr, g_cnt);

    cvtX_kernel<<<(XN4 + 255) / 256, 256>>>(X);                   // 0
    cvtW_wnorm_kernel<<<COMPS / 8, 256>>>(W);                     // 1
    gmat_kernel<<<GRD, GRD>>>(itp);                               // 2
    bmu_b_kernel<<<dim3(COMPS / 128, BSZ / 128), 256, QSMEM>>>(); // 3  (ncu slot 3)
    cudaMemsetAsync(tPtr, 0, (size_t)COMPS * DIM * sizeof(float));
    cudaMemsetAsync(cntPtr, 0, COMPS * sizeof(float));
    bmu_scan_kernel<<<BSZ, 128>>>(X, W);
    scatter_kernel<<<BSZ, 256>>>(X);
    conv_kernel<<<dim3(GRD * DIM / 64, 1), 256>>>(GRD * DIM);
    conv_kernel<<<dim3(DIM / 64, GRD), 256>>>(DIM);
    convs1_kernel<<<GRD, GRD>>>();
    convs2_kernel<<<GRD, GRD>>>();
    final_kernel<<<(COMPS * DIM / 4 + 255) / 256, 256>>>(W, out, itp);
}

// round 15
// speedup vs baseline: 1.5621x; 1.5621x over previous
#include <cuda_runtime.h>
#include <cuda_bf16.h>
#include <math.h>
#include <cstdint>

#define BSZ   4096
#define DIM   768
#define COMPS 16384
#define GRD   128

// ---------------- device scratch ----------------
__device__ float g_T[COMPS * DIM];
__device__ float g_wn[COMPS];
__device__ float g_cnt[COMPS];
__device__ float g_s1[COMPS];
__device__ float g_s[COMPS];
__device__ float g_G[GRD * GRD];
__device__ int   g_bmu[BSZ];
__device__ __align__(16) __nv_bfloat16 g_Xb[BSZ * DIM];
__device__ __align__(16) __nv_bfloat16 g_Wb[COMPS * DIM];
__device__ __align__(16) float4 g_top2[(size_t)BSZ * 128];   // per (row, coltile): v0,i0,v1,i1

// ---------------- helpers ----------------
__device__ __forceinline__ uint32_t smem_to_u32(const void* p) {
    uint32_t a;
    asm("{ .reg .u64 t; cvta.to.shared.u64 t, %1; cvt.u32.u64 %0, t; }" : "=r"(a) : "l"(p));
    return a;
}
__device__ __forceinline__ void cp_async16(uint32_t dst, const void* src) {
    asm volatile("cp.async.cg.shared.global [%0], [%1], 16;" :: "r"(dst), "l"(src));
}
__device__ __forceinline__ void ldmatrix_x4(uint32_t& r0, uint32_t& r1, uint32_t& r2,
                                            uint32_t& r3, uint32_t addr) {
    asm volatile("ldmatrix.sync.aligned.m8n8.x4.shared.b16 {%0,%1,%2,%3}, [%4];"
                 : "=r"(r0), "=r"(r1), "=r"(r2), "=r"(r3) : "r"(addr));
}
__device__ __forceinline__ void mma_bf16(float* d, const uint32_t* a, const uint32_t* b) {
    asm volatile(
        "mma.sync.aligned.m16n8k16.row.col.f32.bf16.bf16.f32 "
        "{%0,%1,%2,%3}, {%4,%5,%6,%7}, {%8,%9}, {%0,%1,%2,%3};"
        : "+f"(d[0]), "+f"(d[1]), "+f"(d[2]), "+f"(d[3])
        : "r"(a[0]), "r"(a[1]), "r"(a[2]), "r"(a[3]), "r"(b[0]), "r"(b[1]));
}
__device__ __forceinline__ unsigned long long pack2(float lo, float hi) {
    unsigned long long r;
    asm("mov.b64 %0, {%1, %2};" : "=l"(r) : "r"(__float_as_uint(lo)), "r"(__float_as_uint(hi)));
    return r;
}
__device__ __forceinline__ void ffma2(unsigned long long& d, unsigned long long a,
                                      unsigned long long b) {
    asm("fma.rn.f32x2 %0, %1, %2, %0;" : "+l"(d) : "l"(a), "l"(b));
}
__device__ __forceinline__ void unpack2(unsigned long long p, float& lo, float& hi) {
    unsigned l, h;
    asm("mov.b64 {%0, %1}, %2;" : "=r"(l), "=r"(h) : "l"(p));
    lo = __uint_as_float(l); hi = __uint_as_float(h);
}

// ---------------- pre kernels ----------------
#define XN4 (BSZ * DIM / 4)
#define WN4 (COMPS * DIM / 4)

__global__ void cvtX_kernel(const float* __restrict__ src) {
    int i = blockIdx.x * blockDim.x + threadIdx.x;
    if (i >= XN4) return;
    float4 v = *(const float4*)(src + (size_t)i * 4);
    ushort4 o;
    o.x = __bfloat16_as_ushort(__float2bfloat16(v.x));
    o.y = __bfloat16_as_ushort(__float2bfloat16(v.y));
    o.z = __bfloat16_as_ushort(__float2bfloat16(v.z));
    o.w = __bfloat16_as_ushort(__float2bfloat16(v.w));
    *(ushort4*)(g_Xb + (size_t)i * 4) = o;
}

__global__ void cvtW_wnorm_kernel(const float* __restrict__ W) {
    int row = blockIdx.x * 8 + (threadIdx.x >> 5);
    int lane = threadIdx.x & 31;
    const float* wr = W + (size_t)row * DIM;
    float s = 0.f;
    #pragma unroll
    for (int k = 0; k < 6; k++) {
        int e = lane * 4 + k * 128;
        float4 v = *(const float4*)(wr + e);
        s = fmaf(v.x, v.x, s); s = fmaf(v.y, v.y, s);
        s = fmaf(v.z, v.z, s); s = fmaf(v.w, v.w, s);
        ushort4 o;
        o.x = __bfloat16_as_ushort(__float2bfloat16(v.x));
        o.y = __bfloat16_as_ushort(__float2bfloat16(v.y));
        o.z = __bfloat16_as_ushort(__float2bfloat16(v.z));
        o.w = __bfloat16_as_ushort(__float2bfloat16(v.w));
        *(ushort4*)(g_Wb + (size_t)row * DIM + e) = o;
    }
    #pragma unroll
    for (int o = 16; o; o >>= 1) s += __shfl_xor_sync(0xffffffffu, s, o);
    if (lane == 0) g_wn[row] = s;
}

__global__ void gmat_kernel(const int* __restrict__ itp) {
    float decay = 1.f - (float)(*itp) / 1000.f;
    float sig = 64.f * decay;
    int a = blockIdx.x, b = threadIdx.x;
    float d = (float)(a - b);
    g_G[a * GRD + b] = expf(-(d * d) / (sig * sig));
}

// ---------------- bf16 BMU GEMM: 128x128 tiles, 2 CTAs/SM, 3 stages ------
// K chunk = 32 halfs = 64B/row, pitch 80B (ldmatrix conflict-free).
// Stage = A 10240 + B 10240 = 20480. 3 stages + wns = 61952 B.
#define QPITCH  80
#define QT_TILE 10240
#define QSTAGE  20480
#define QWNS    (3 * QSTAGE)     // 61440
#define QSMEM   (QWNS + 512)     // 61952
#define NKCH    (DIM / 32)       // 24

#define INS2(v, i)                                            \
    do {                                                      \
        float _v = (v); int _i = (i);                         \
        if (_v < v0) { v1 = v0; i1 = i0; v0 = _v; i0 = _i; }  \
        else if (_v < v1) { v1 = _v; i1 = _i; }               \
    } while (0)

__global__ __launch_bounds__(256, 2) void bmu_b_kernel() {
    extern __shared__ char sm[];
    const uint32_t sb = smem_to_u32(sm);
    const int t = threadIdx.x, lane = t & 31, w = t >> 5;
    const int wm = w >> 2, wn_ = w & 3;
    const int arow = lane >> 2;
    const int bx = blockIdx.x, by = blockIdx.y;
    const int rowX = by * 128, rowW = bx * 128;

    float* wns = (float*)(sm + QWNS);
    if (t < 128) wns[t] = g_wn[rowW + t];

    // ldmatrix lane-offsets (bytes into tile), per k16-step add 32
    const int alr = lane & 15, ahalf = (lane >> 4) * 16;
    uint32_t aoff[4];
    #pragma unroll
    for (int mi = 0; mi < 4; mi++)
        aoff[mi] = (uint32_t)((wm * 64 + mi * 16 + alr) * QPITCH + ahalf);
    const int blr = lane & 7, bk = ((lane >> 3) & 1) * 16, bhi = lane >> 4;
    uint32_t boff[2];
    #pragma unroll
    for (int pi = 0; pi < 2; pi++)
        boff[pi] = (uint32_t)((wn_ * 32 + (2 * pi + bhi) * 8 + blr) * QPITCH + bk);

    float acc[4][4][4];
    #pragma unroll
    for (int mi = 0; mi < 4; mi++)
        #pragma unroll
        for (int ni = 0; ni < 4; ni++)
            #pragma unroll
            for (int k = 0; k < 4; k++) acc[mi][ni][k] = 0.f;

    auto load_stage = [&](int s, int c) {
        uint32_t base = sb + s * QSTAGE;
        #pragma unroll
        for (int i = 0; i < 2; i++) {
            int idx = t + i * 256;
            int r = idx >> 2, g = idx & 3;       // 4 x 16B granules per 64B row
            uint32_t so = (uint32_t)(r * QPITCH + g * 16);
            cp_async16(base + so,
                       g_Xb + (size_t)(rowX + r) * DIM + c * 32 + g * 8);
            cp_async16(base + QT_TILE + so,
                       g_Wb + (size_t)(rowW + r) * DIM + c * 32 + g * 8);
        }
    };
    auto compute = [&](int s) {
        uint32_t Ah = sb + s * QSTAGE;
        uint32_t Bh = Ah + QT_TILE;
        #pragma unroll
        for (int step = 0; step < 2; step++) {
            uint32_t ko = step * 32;
            uint32_t b[4][2];
            ldmatrix_x4(b[0][0], b[0][1], b[1][0], b[1][1], Bh + boff[0] + ko);
            ldmatrix_x4(b[2][0], b[2][1], b[3][0], b[3][1], Bh + boff[1] + ko);
            uint32_t a[4][4];
            #pragma unroll
            for (int mi = 0; mi < 4; mi++)
                ldmatrix_x4(a[mi][0], a[mi][1], a[mi][2], a[mi][3], Ah + aoff[mi] + ko);
            #pragma unroll
            for (int mi = 0; mi < 4; mi++)
                #pragma unroll
                for (int ni = 0; ni < 4; ni++) mma_bf16(acc[mi][ni], a[mi], b[ni]);
        }
    };

    load_stage(0, 0);
    asm volatile("cp.async.commit_group;");
    load_stage(1, 1);
    asm volatile("cp.async.commit_group;");
    for (int c = 0; c < NKCH; c++) {
        asm volatile("cp.async.wait_group 1;");
        __syncthreads();
        if (c + 2 < NKCH) {
            load_stage((c + 2) % 3, c + 2);
            asm volatile("cp.async.commit_group;");
        }
        compute(c % 3);
        __syncthreads();
    }

    // ---- epilogue: per-row top-2 of d2 = wn - 2*dot over 128 cols ----
    float4* top2s = (float4*)sm;           // [128 rows][4 warps]

    #pragma unroll
    for (int mi = 0; mi < 4; mi++) {
        #pragma unroll
        for (int h = 0; h < 2; h++) {
            float v0 = 3.4e38f, v1 = 3.4e38f;
            int i0 = 0x7fffffff, i1 = 0x7fffffff;
            #pragma unroll
            for (int ni = 0; ni < 4; ni++) {
                #pragma unroll
                for (int cc = 0; cc < 2; cc++) {
                    int col = wn_ * 32 + ni * 8 + (lane & 3) * 2 + cc;
                    float d2 = wns[col] - 2.f * acc[mi][ni][h * 2 + cc];
                    INS2(d2, rowW + col);
                }
            }
            #pragma unroll
            for (int o = 1; o < 4; o <<= 1) {
                float ov0 = __shfl_xor_sync(0xffffffffu, v0, o);
                int   oi0 = __shfl_xor_sync(0xffffffffu, i0, o);
                float ov1 = __shfl_xor_sync(0xffffffffu, v1, o);
                int   oi1 = __shfl_xor_sync(0xffffffffu, i1, o);
                INS2(ov0, oi0);
                INS2(ov1, oi1);
            }
            if ((lane & 3) == 0) {
                int rr = wm * 64 + mi * 16 + h * 8 + arow;
                top2s[rr * 4 + wn_] = make_float4(v0, __int_as_float(i0),
                                                  v1, __int_as_float(i1));
            }
        }
    }
    __syncthreads();
    if (t < 128) {
        float4 a0 = top2s[t * 4 + 0];
        float v0 = a0.x, v1 = a0.z;
        int i0 = __float_as_int(a0.y), i1 = __float_as_int(a0.w);
        #pragma unroll
        for (int j = 1; j < 4; j++) {
            float4 aj = top2s[t * 4 + j];
            INS2(aj.x, __float_as_int(aj.y));
            INS2(aj.z, __float_as_int(aj.w));
        }
        g_top2[(size_t)(rowX + t) * 128 + bx] =
            make_float4(v0, __int_as_float(i0), v1, __int_as_float(i1));
    }
}

// ---------------- candidate rescue: min + margin over top-2 + exact fp32 --
#define MARGIN_F 2.0f
__global__ __launch_bounds__(128) void bmu_scan_kernel(const float* __restrict__ X,
                                                       const float* __restrict__ W) {
    __shared__ float red[128];
    __shared__ int cnt;
    __shared__ int cand[128];
    int row = blockIdx.x, t = threadIdx.x;
    float4 e = g_top2[(size_t)row * 128 + t];

    red[t] = e.x;
    __syncthreads();
    for (int s = 64; s; s >>= 1) {
        if (t < s) red[t] = fminf(red[t], red[t + s]);
        __syncthreads();
    }
    float thr = red[0] + MARGIN_F;
    if (t == 0) cnt = 0;
    __syncthreads();
    if (e.x <= thr) { int p = atomicAdd(&cnt, 1); if (p < 128) cand[p] = __float_as_int(e.y); }
    if (e.z <= thr) { int p = atomicAdd(&cnt, 1); if (p < 128) cand[p] = __float_as_int(e.w); }
    __syncthreads();
    int n = min(cnt, 128);
    if (t < 32) {
        const float* xr = X + (size_t)row * DIM;
        float bv = 3.4e38f; int bi = 0x7fffffff;
        for (int k = 0; k < n; k++) {
            int c = cand[k];
            const float* wr = W + (size_t)c * DIM;
            float s = 0.f;
            #pragma unroll
            for (int m = 0; m < 24; m++)
                s = fmaf(xr[t + m * 32], wr[t + m * 32], s);
            #pragma unroll
            for (int o = 16; o; o >>= 1) s += __shfl_xor_sync(0xffffffffu, s, o);
            float d2 = g_wn[c] - 2.f * s;
            if (d2 < bv || (d2 == bv && c < bi)) { bv = d2; bi = c; }
        }
        if (t == 0) g_bmu[row] = bi;
    }
}

__global__ void scatter_kernel(const float* __restrict__ X) {
    int b = blockIdx.x;
    int u = g_bmu[b];
    const float* xr = X + (size_t)b * DIM;
    float* tr = g_T + (size_t)u * DIM;
    for (int d = threadIdx.x; d < DIM; d += blockDim.x)
        atomicAdd(&tr[d], xr[d]);
    if (threadIdx.x == 0) atomicAdd(&g_cnt[u], 1.f);
}

// ---------------- separable Gaussian conv via packed f32x2, in place ------
__global__ __launch_bounds__(256) void conv_kernel(int rstride) {
    __shared__ float Ts[16][64];
    __shared__ float Gs[16][128];
    int t = threadIdx.x;
    size_t base = (size_t)blockIdx.y * (GRD * DIM) + (size_t)blockIdx.x * 64;
    int cg = t & 15, rg = t >> 4;
    int lk = t >> 4, lc = (t & 15) * 4, gi = (t & 15) * 8;

    unsigned long long acc2[8][2];
    #pragma unroll
    for (int r = 0; r < 8; r++) { acc2[r][0] = 0ull; acc2[r][1] = 0ull; }

    for (int k0 = 0; k0 < GRD; k0 += 16) {
        if (k0) __syncthreads();
        *(float4*)&Ts[lk][lc]     = *(const float4*)&g_T[base + (size_t)(k0 + lk) * rstride + lc];
        *(float4*)&Gs[lk][gi]     = *(const float4*)&g_G[(k0 + lk) * GRD + gi];
        *(float4*)&Gs[lk][gi + 4] = *(const float4*)&g_G[(k0 + lk) * GRD + gi + 4];
        __syncthreads();
        #pragma unroll
        for (int k = 0; k < 16; k++) {
            float4 tv = *(const float4*)&Ts[k][cg * 4];
            unsigned long long b0 = pack2(tv.x, tv.y);
            unsigned long long b1 = pack2(tv.z, tv.w);
            #pragma unroll
            for (int r = 0; r < 8; r++) {
                float g = Gs[k][rg * 8 + r];
                unsigned long long gp = pack2(g, g);
                ffma2(acc2[r][0], gp, b0);
                ffma2(acc2[r][1], gp, b1);
            }
        }
    }
    #pragma unroll
    for (int r = 0; r < 8; r++) {
        float4 o;
        unpack2(acc2[r][0], o.x, o.y);
        unpack2(acc2[r][1], o.z, o.w);
        *(float4*)&g_T[base + (size_t)(rg * 8 + r) * rstride + cg * 4] = o;
    }
}

__global__ void convs1_kernel() {
    int ip = blockIdx.x, j = threadIdx.x;
    float s = 0.f;
    for (int i = 0; i < GRD; i++)
        s = fmaf(g_G[ip * GRD + i], g_cnt[i * GRD + j], s);
    g_s1[ip * GRD + j] = s;
}
__global__ void convs2_kernel() {
    int i = blockIdx.x, jp = threadIdx.x;
    float s = 0.f;
    for (int j = 0; j < GRD; j++)
        s = fmaf(g_G[j * GRD + jp], g_s1[i * GRD + j], s);
    g_s[i * GRD + jp] = s;
}

__global__ void final_kernel(const float* __restrict__ W, float* __restrict__ out,
                             const int* __restrict__ itp) {
    float decay = 1.f - (float)(*itp) / 1000.f;
    float alpha = 0.3f * decay;
    int idx = blockIdx.x * blockDim.x + threadIdx.x;
    int i4 = idx * 4;
    if (i4 >= COMPS * DIM) return;
    int c = i4 / DIM;
    float m = 1.f - alpha * g_s[c];
    float4 w = *(const float4*)(W + i4);
    float4 v = *(const float4*)(g_T + i4);
    float4 o = make_float4(w.x * m + alpha * v.x, w.y * m + alpha * v.y,
                           w.z * m + alpha * v.z, w.w * m + alpha * v.w);
    *(float4*)(out + i4) = o;
}

// ---------------- launch ----------------
extern "C" void kernel_launch(void* const* d_in, const int* in_sizes, int n_in,
                              void* d_out, int out_size) {
    const float* X   = (const float*)d_in[0];
    const float* W   = (const float*)d_in[1];
    const int*   itp = (const int*)d_in[2];
    float* out = (float*)d_out;

    cudaFuncSetAttribute(bmu_b_kernel, cudaFuncAttributeMaxDynamicSharedMemorySize, QSMEM);

    float *tPtr, *cntPtr;
    cudaGetSymbolAddress((void**)&tPtr, g_T);
    cudaGetSymbolAddress((void**)&cntPtr, g_cnt);

    cvtX_kernel<<<(XN4 + 255) / 256, 256>>>(X);                   // 0
    cvtW_wnorm_kernel<<<COMPS / 8, 256>>>(W);                     // 1
    gmat_kernel<<<GRD, GRD>>>(itp);                               // 2
    bmu_b_kernel<<<dim3(COMPS / 128, BSZ / 128), 256, QSMEM>>>(); // 3  (ncu slot 3)
    cudaMemsetAsync(tPtr, 0, (size_t)COMPS * DIM * sizeof(float));
    cudaMemsetAsync(cntPtr, 0, COMPS * sizeof(float));
    bmu_scan_kernel<<<BSZ, 128>>>(X, W);
    scatter_kernel<<<BSZ, 256>>>(X);
    conv_kernel<<<dim3(GRD * DIM / 64, 1), 256>>>(GRD * DIM);
    conv_kernel<<<dim3(DIM / 64, GRD), 256>>>(DIM);
    convs1_kernel<<<GRD, GRD>>>();
    convs2_kernel<<<GRD, GRD>>>();
    final_kernel<<<(COMPS * DIM / 4 + 255) / 256, 256>>>(W, out, itp);
}

// round 17
// speedup vs baseline: 1.5796x; 1.0112x over previous
#include <cuda_runtime.h>
#include <cuda_bf16.h>
#include <math.h>
#include <cstdint>

#define BSZ   4096
#define DIM   768
#define COMPS 16384
#define GRD   128

// ---------------- device scratch ----------------
__device__ float g_T[COMPS * DIM];
__device__ float g_wn[COMPS];
__device__ float g_cnt[COMPS];
__device__ float g_s1[COMPS];
__device__ float g_s[COMPS];
__device__ float g_G[GRD * GRD];
__device__ int   g_bmu[BSZ];
__device__ __align__(16) __nv_bfloat16 g_Xb[BSZ * DIM];
__device__ __align__(16) __nv_bfloat16 g_Wb[COMPS * DIM];
__device__ __align__(16) float4 g_top2[(size_t)BSZ * 128];   // per (row, coltile): v0,i0,v1,i1

// ---------------- helpers ----------------
__device__ __forceinline__ uint32_t smem_to_u32(const void* p) {
    uint32_t a;
    asm("{ .reg .u64 t; cvta.to.shared.u64 t, %1; cvt.u32.u64 %0, t; }" : "=r"(a) : "l"(p));
    return a;
}
__device__ __forceinline__ void cp_async16(uint32_t dst, const void* src) {
    asm volatile("cp.async.cg.shared.global [%0], [%1], 16;" :: "r"(dst), "l"(src));
}
__device__ __forceinline__ void ldmatrix_x4(uint32_t& r0, uint32_t& r1, uint32_t& r2,
                                            uint32_t& r3, uint32_t addr) {
    asm volatile("ldmatrix.sync.aligned.m8n8.x4.shared.b16 {%0,%1,%2,%3}, [%4];"
                 : "=r"(r0), "=r"(r1), "=r"(r2), "=r"(r3) : "r"(addr));
}
__device__ __forceinline__ void mma_bf16(float* d, const uint32_t* a, const uint32_t* b) {
    asm volatile(
        "mma.sync.aligned.m16n8k16.row.col.f32.bf16.bf16.f32 "
        "{%0,%1,%2,%3}, {%4,%5,%6,%7}, {%8,%9}, {%0,%1,%2,%3};"
        : "+f"(d[0]), "+f"(d[1]), "+f"(d[2]), "+f"(d[3])
        : "r"(a[0]), "r"(a[1]), "r"(a[2]), "r"(a[3]), "r"(b[0]), "r"(b[1]));
}
__device__ __forceinline__ unsigned long long pack2(float lo, float hi) {
    unsigned long long r;
    asm("mov.b64 %0, {%1, %2};" : "=l"(r) : "r"(__float_as_uint(lo)), "r"(__float_as_uint(hi)));
    return r;
}
__device__ __forceinline__ void ffma2(unsigned long long& d, unsigned long long a,
                                      unsigned long long b) {
    asm("fma.rn.f32x2 %0, %1, %2, %0;" : "+l"(d) : "l"(a), "l"(b));
}
__device__ __forceinline__ void unpack2(unsigned long long p, float& lo, float& hi) {
    unsigned l, h;
    asm("mov.b64 {%0, %1}, %2;" : "=r"(l), "=r"(h) : "l"(p));
    lo = __uint_as_float(l); hi = __uint_as_float(h);
}

// ---------------- pre kernels ----------------
#define XN4 (BSZ * DIM / 4)
#define WN4 (COMPS * DIM / 4)

__global__ void cvtX_kernel(const float* __restrict__ src) {
    int i = blockIdx.x * blockDim.x + threadIdx.x;
    if (i >= XN4) return;
    float4 v = *(const float4*)(src + (size_t)i * 4);
    ushort4 o;
    o.x = __bfloat16_as_ushort(__float2bfloat16(v.x));
    o.y = __bfloat16_as_ushort(__float2bfloat16(v.y));
    o.z = __bfloat16_as_ushort(__float2bfloat16(v.z));
    o.w = __bfloat16_as_ushort(__float2bfloat16(v.w));
    *(ushort4*)(g_Xb + (size_t)i * 4) = o;
}

__global__ void cvtW_wnorm_kernel(const float* __restrict__ W) {
    int row = blockIdx.x * 8 + (threadIdx.x >> 5);
    int lane = threadIdx.x & 31;
    const float* wr = W + (size_t)row * DIM;
    float s = 0.f;
    #pragma unroll
    for (int k = 0; k < 6; k++) {
        int e = lane * 4 + k * 128;
        float4 v = *(const float4*)(wr + e);
        s = fmaf(v.x, v.x, s); s = fmaf(v.y, v.y, s);
        s = fmaf(v.z, v.z, s); s = fmaf(v.w, v.w, s);
        ushort4 o;
        o.x = __bfloat16_as_ushort(__float2bfloat16(v.x));
        o.y = __bfloat16_as_ushort(__float2bfloat16(v.y));
        o.z = __bfloat16_as_ushort(__float2bfloat16(v.z));
        o.w = __bfloat16_as_ushort(__float2bfloat16(v.w));
        *(ushort4*)(g_Wb + (size_t)row * DIM + e) = o;
    }
    #pragma unroll
    for (int o = 16; o; o >>= 1) s += __shfl_xor_sync(0xffffffffu, s, o);
    if (lane == 0) g_wn[row] = s;
}

__global__ void gmat_kernel(const int* __restrict__ itp) {
    float decay = 1.f - (float)(*itp) / 1000.f;
    float sig = 64.f * decay;
    int a = blockIdx.x, b = threadIdx.x;
    float d = (float)(a - b);
    g_G[a * GRD + b] = expf(-(d * d) / (sig * sig));
}

// ---------------- bf16 BMU GEMM: 128x128 tiles, 2 CTAs/SM, 3 stages ------
// K chunk = 32 halfs = 64B/row, pitch 80B (ldmatrix conflict-free).
// ONE barrier per iteration (top-of-loop, after wait_group) — sufficient:
// it proves all warps finished compute(c-1) before load targets (c-1)%3.
#define QPITCH  80
#define QT_TILE 10240
#define QSTAGE  20480
#define QWNS    (3 * QSTAGE)     // 61440
#define QSMEM   (QWNS + 512)     // 61952
#define NKCH    (DIM / 32)       // 24

#define INS2(v, i)                                            \
    do {                                                      \
        float _v = (v); int _i = (i);                         \
        if (_v < v0) { v1 = v0; i1 = i0; v0 = _v; i0 = _i; }  \
        else if (_v < v1) { v1 = _v; i1 = _i; }               \
    } while (0)

__global__ __launch_bounds__(256, 2) void bmu_b_kernel() {
    extern __shared__ char sm[];
    const uint32_t sb = smem_to_u32(sm);
    const int t = threadIdx.x, lane = t & 31, w = t >> 5;
    const int wm = w >> 2, wn_ = w & 3;
    const int arow = lane >> 2;
    const int bx = blockIdx.x, by = blockIdx.y;
    const int rowX = by * 128, rowW = bx * 128;

    float* wns = (float*)(sm + QWNS);
    if (t < 128) wns[t] = g_wn[rowW + t];

    // ldmatrix lane-offsets (bytes into tile), per k16-step add 32
    const int alr = lane & 15, ahalf = (lane >> 4) * 16;
    uint32_t aoff[4];
    #pragma unroll
    for (int mi = 0; mi < 4; mi++)
        aoff[mi] = (uint32_t)((wm * 64 + mi * 16 + alr) * QPITCH + ahalf);
    const int blr = lane & 7, bk = ((lane >> 3) & 1) * 16, bhi = lane >> 4;
    uint32_t boff[2];
    #pragma unroll
    for (int pi = 0; pi < 2; pi++)
        boff[pi] = (uint32_t)((wn_ * 32 + (2 * pi + bhi) * 8 + blr) * QPITCH + bk);

    float acc[4][4][4];
    #pragma unroll
    for (int mi = 0; mi < 4; mi++)
        #pragma unroll
        for (int ni = 0; ni < 4; ni++)
            #pragma unroll
            for (int k = 0; k < 4; k++) acc[mi][ni][k] = 0.f;

    auto load_stage = [&](int s, int c) {
        uint32_t base = sb + s * QSTAGE;
        #pragma unroll
        for (int i = 0; i < 2; i++) {
            int idx = t + i * 256;
            int r = idx >> 2, g = idx & 3;       // 4 x 16B granules per 64B row
            uint32_t so = (uint32_t)(r * QPITCH + g * 16);
            cp_async16(base + so,
                       g_Xb + (size_t)(rowX + r) * DIM + c * 32 + g * 8);
            cp_async16(base + QT_TILE + so,
                       g_Wb + (size_t)(rowW + r) * DIM + c * 32 + g * 8);
        }
    };
    auto compute = [&](int s) {
        uint32_t Ah = sb + s * QSTAGE;
        uint32_t Bh = Ah + QT_TILE;
        #pragma unroll
        for (int step = 0; step < 2; step++) {
            uint32_t ko = step * 32;
            uint32_t b[4][2];
            ldmatrix_x4(b[0][0], b[0][1], b[1][0], b[1][1], Bh + boff[0] + ko);
            ldmatrix_x4(b[2][0], b[2][1], b[3][0], b[3][1], Bh + boff[1] + ko);
            uint32_t a[4][4];
            #pragma unroll
            for (int mi = 0; mi < 4; mi++)
                ldmatrix_x4(a[mi][0], a[mi][1], a[mi][2], a[mi][3], Ah + aoff[mi] + ko);
            #pragma unroll
            for (int mi = 0; mi < 4; mi++)
                #pragma unroll
                for (int ni = 0; ni < 4; ni++) mma_bf16(acc[mi][ni], a[mi], b[ni]);
        }
    };

    load_stage(0, 0);
    asm volatile("cp.async.commit_group;");
    load_stage(1, 1);
    asm volatile("cp.async.commit_group;");
    for (int c = 0; c < NKCH; c++) {
        asm volatile("cp.async.wait_group 1;");
        __syncthreads();                       // all warps done with compute(c-1)
        if (c + 2 < NKCH) {
            load_stage((c + 2) % 3, c + 2);    // overwrites buffer (c-1)%3 — safe
            asm volatile("cp.async.commit_group;");
        }
        compute(c % 3);
    }

    // ---- epilogue: per-row top-2 of d2 = wn - 2*dot over 128 cols ----
    __syncthreads();                           // stage smem free for reuse
    float4* top2s = (float4*)sm;               // [128 rows][4 warps]

    #pragma unroll
    for (int mi = 0; mi < 4; mi++) {
        #pragma unroll
        for (int h = 0; h < 2; h++) {
            float v0 = 3.4e38f, v1 = 3.4e38f;
            int i0 = 0x7fffffff, i1 = 0x7fffffff;
            #pragma unroll
            for (int ni = 0; ni < 4; ni++) {
                #pragma unroll
                for (int cc = 0; cc < 2; cc++) {
                    int col = wn_ * 32 + ni * 8 + (lane & 3) * 2 + cc;
                    float d2 = wns[col] - 2.f * acc[mi][ni][h * 2 + cc];
                    INS2(d2, rowW + col);
                }
            }
            #pragma unroll
            for (int o = 1; o < 4; o <<= 1) {
                float ov0 = __shfl_xor_sync(0xffffffffu, v0, o);
                int   oi0 = __shfl_xor_sync(0xffffffffu, i0, o);
                float ov1 = __shfl_xor_sync(0xffffffffu, v1, o);
                int   oi1 = __shfl_xor_sync(0xffffffffu, i1, o);
                INS2(ov0, oi0);
                INS2(ov1, oi1);
            }
            if ((lane & 3) == 0) {
                int rr = wm * 64 + mi * 16 + h * 8 + arow;
                top2s[rr * 4 + wn_] = make_float4(v0, __int_as_float(i0),
                                                  v1, __int_as_float(i1));
            }
        }
    }
    __syncthreads();
    if (t < 128) {
        float4 a0 = top2s[t * 4 + 0];
        float v0 = a0.x, v1 = a0.z;
        int i0 = __float_as_int(a0.y), i1 = __float_as_int(a0.w);
        #pragma unroll
        for (int j = 1; j < 4; j++) {
            float4 aj = top2s[t * 4 + j];
            INS2(aj.x, __float_as_int(aj.y));
            INS2(aj.z, __float_as_int(aj.w));
        }
        g_top2[(size_t)(rowX + t) * 128 + bx] =
            make_float4(v0, __int_as_float(i0), v1, __int_as_float(i1));
    }
}

// ---------------- candidate rescue: min + margin over top-2 + exact fp32 --
#define MARGIN_F 2.0f
__global__ __launch_bounds__(128) void bmu_scan_kernel(const float* __restrict__ X,
                                                       const float* __restrict__ W) {
    __shared__ float red[128];
    __shared__ int cnt;
    __shared__ int cand[128];
    int row = blockIdx.x, t = threadIdx.x;
    float4 e = g_top2[(size_t)row * 128 + t];

    red[t] = e.x;
    __syncthreads();
    for (int s = 64; s; s >>= 1) {
        if (t < s) red[t] = fminf(red[t], red[t + s]);
        __syncthreads();
    }
    float thr = red[0] + MARGIN_F;
    if (t == 0) cnt = 0;
    __syncthreads();
    if (e.x <= thr) { int p = atomicAdd(&cnt, 1); if (p < 128) cand[p] = __float_as_int(e.y); }
    if (e.z <= thr) { int p = atomicAdd(&cnt, 1); if (p < 128) cand[p] = __float_as_int(e.w); }
    __syncthreads();
    int n = min(cnt, 128);
    if (t < 32) {
        const float* xr = X + (size_t)row * DIM;
        float bv = 3.4e38f; int bi = 0x7fffffff;
        for (int k = 0; k < n; k++) {
            int c = cand[k];
            const float* wr = W + (size_t)c * DIM;
            float s = 0.f;
            #pragma unroll
            for (int m = 0; m < 24; m++)
                s = fmaf(xr[t + m * 32], wr[t + m * 32], s);
            #pragma unroll
            for (int o = 16; o; o >>= 1) s += __shfl_xor_sync(0xffffffffu, s, o);
            float d2 = g_wn[c] - 2.f * s;
            if (d2 < bv || (d2 == bv && c < bi)) { bv = d2; bi = c; }
        }
        if (t == 0) g_bmu[row] = bi;
    }
}

__global__ void scatter_kernel(const float* __restrict__ X) {
    int b = blockIdx.x;
    int u = g_bmu[b];
    const float* xr = X + (size_t)b * DIM;
    float* tr = g_T + (size_t)u * DIM;
    for (int d = threadIdx.x; d < DIM; d += blockDim.x)
        atomicAdd(&tr[d], xr[d]);
    if (threadIdx.x == 0) atomicAdd(&g_cnt[u], 1.f);
}

// ---------------- separable Gaussian conv via packed f32x2, in place ------
__global__ __launch_bounds__(256) void conv_kernel(int rstride) {
    __shared__ float Ts[16][64];
    __shared__ float Gs[16][128];
    int t = threadIdx.x;
    size_t base = (size_t)blockIdx.y * (GRD * DIM) + (size_t)blockIdx.x * 64;
    int cg = t & 15, rg = t >> 4;
    int lk = t >> 4, lc = (t & 15) * 4, gi = (t & 15) * 8;

    unsigned long long acc2[8][2];
    #pragma unroll
    for (int r = 0; r < 8; r++) { acc2[r][0] = 0ull; acc2[r][1] = 0ull; }

    for (int k0 = 0; k0 < GRD; k0 += 16) {
        if (k0) __syncthreads();
        *(float4*)&Ts[lk][lc]     = *(const float4*)&g_T[base + (size_t)(k0 + lk) * rstride + lc];
        *(float4*)&Gs[lk][gi]     = *(const float4*)&g_G[(k0 + lk) * GRD + gi];
        *(float4*)&Gs[lk][gi + 4] = *(const float4*)&g_G[(k0 + lk) * GRD + gi + 4];
        __syncthreads();
        #pragma unroll
        for (int k = 0; k < 16; k++) {
            float4 tv = *(const float4*)&Ts[k][cg * 4];
            unsigned long long b0 = pack2(tv.x, tv.y);
            unsigned long long b1 = pack2(tv.z, tv.w);
            #pragma unroll
            for (int r = 0; r < 8; r++) {
                float g = Gs[k][rg * 8 + r];
                unsigned long long gp = pack2(g, g);
                ffma2(acc2[r][0], gp, b0);
                ffma2(acc2[r][1], gp, b1);
            }
        }
    }
    #pragma unroll
    for (int r = 0; r < 8; r++) {
        float4 o;
        unpack2(acc2[r][0], o.x, o.y);
        unpack2(acc2[r][1], o.z, o.w);
        *(float4*)&g_T[base + (size_t)(rg * 8 + r) * rstride + cg * 4] = o;
    }
}

__global__ void convs1_kernel() {
    int ip = blockIdx.x, j = threadIdx.x;
    float s = 0.f;
    for (int i = 0; i < GRD; i++)
        s = fmaf(g_G[ip * GRD + i], g_cnt[i * GRD + j], s);
    g_s1[ip * GRD + j] = s;
}
__global__ void convs2_kernel() {
    int i = blockIdx.x, jp = threadIdx.x;
    float s = 0.f;
    for (int j = 0; j < GRD; j++)
        s = fmaf(g_G[j * GRD + jp], g_s1[i * GRD + j], s);
    g_s[i * GRD + jp] = s;
}

__global__ void final_kernel(const float* __restrict__ W, float* __restrict__ out,
                             const int* __restrict__ itp) {
    float decay = 1.f - (float)(*itp) / 1000.f;
    float alpha = 0.3f * decay;
    int idx = blockIdx.x * blockDim.x + threadIdx.x;
    int i4 = idx * 4;
    if (i4 >= COMPS * DIM) return;
    int c = i4 / DIM;
    float m = 1.f - alpha * g_s[c];
    float4 w = *(const float4*)(W + i4);
    float4 v = *(const float4*)(g_T + i4);
    float4 o = make_float4(w.x * m + alpha * v.x, w.y * m + alpha * v.y,
                           w.z * m + alpha * v.z, w.w * m + alpha * v.w);
    *(float4*)(out + i4) = o;
}

// ---------------- launch ----------------
extern "C" void kernel_launch(void* const* d_in, const int* in_sizes, int n_in,
                              void* d_out, int out_size) {
    const float* X   = (const float*)d_in[0];
    const float* W   = (const float*)d_in[1];
    const int*   itp = (const int*)d_in[2];
    float* out = (float*)d_out;

    cudaFuncSetAttribute(bmu_b_kernel, cudaFuncAttributeMaxDynamicSharedMemorySize, QSMEM);

    float *tPtr, *cntPtr;
    cudaGetSymbolAddress((void**)&tPtr, g_T);
    cudaGetSymbolAddress((void**)&cntPtr, g_cnt);

    cvtX_kernel<<<(XN4 + 255) / 256, 256>>>(X);                   // 0
    cvtW_wnorm_kernel<<<COMPS / 8, 256>>>(W);                     // 1
    gmat_kernel<<<GRD, GRD>>>(itp);                               // 2
    bmu_b_kernel<<<dim3(COMPS / 128, BSZ / 128), 256, QSMEM>>>(); // 3  (ncu slot 3)
    cudaMemsetAsync(tPtr, 0, (size_t)COMPS * DIM * sizeof(float));
    cudaMemsetAsync(cntPtr, 0, COMPS * sizeof(float));
    bmu_scan_kernel<<<BSZ, 128>>>(X, W);
    scatter_kernel<<<BSZ, 256>>>(X);
    conv_kernel<<<dim3(GRD * DIM / 64, 1), 256>>>(GRD * DIM);
    conv_kernel<<<dim3(DIM / 64, GRD), 256>>>(DIM);
    convs1_kernel<<<GRD, GRD>>>();
    convs2_kernel<<<GRD, GRD>>>();
    final_kernel<<<(COMPS * DIM / 4 + 255) / 256, 256>>>(W, out, itp);
}